// round 1
// baseline (speedup 1.0000x reference)
#include <cuda_runtime.h>
#include <cstdint>

#define Bn 4
#define Cn 16
#define Hn 512
#define Wn 512
#define HWn (Hn*Wn)        // 262144
#define NPIX (Bn*HWn)      // 1048576
#define NOUT (Bn*Cn*HWn)   // 16777216
#define EPSF 1e-10f

// Weight-sum accumulator D, cropped region only (B,H,W). 4 MB static scratch.
__device__ float g_D[NPIX];

// ---------------------------------------------------------------------------
// Kernel 1: zero the output accumulator (d_out) and D.
// ---------------------------------------------------------------------------
__global__ void zero_kernel(float4* __restrict__ out) {
    const int n_out4 = NOUT / 4;   // 4194304
    const int n_d4   = NPIX / 4;   // 262144
    int idx = blockIdx.x * blockDim.x + threadIdx.x;
    float4 z = make_float4(0.f, 0.f, 0.f, 0.f);
    if (idx < n_out4) {
        out[idx] = z;
    } else if (idx < n_out4 + n_d4) {
        reinterpret_cast<float4*>(g_D)[idx - n_out4] = z;
    }
}

// ---------------------------------------------------------------------------
// Kernel 2: scatter. One thread per source pixel (b,i,j).
// Computes the 4 bilinear corners once, reuses them across all 16 channels.
// Scatters directly into d_out (the crop [1:h+1,1:w+1] of the padded A),
// skipping corners that the reference crops away.
// ---------------------------------------------------------------------------
__global__ void scatter_kernel(const float* __restrict__ x,
                               const float* __restrict__ grid,
                               float* __restrict__ out) {
    int p = blockIdx.x * blockDim.x + threadIdx.x;
    if (p >= NPIX) return;

    float2 gv = reinterpret_cast<const float2*>(grid)[p];

    // g = (v+1)*0.5 ; gi = clip(g*h + 1, 0, h+1-2*EPS)  (f32: bound == 513.0f)
    float g0 = (gv.x + 1.0f) * 0.5f;
    float g1 = (gv.y + 1.0f) * 0.5f;
    float gi = fminf(fmaxf(fmaf(g0, 512.0f, 1.0f), 0.0f), 513.0f);
    float gj = fminf(fmaxf(fmaf(g1, 512.0f, 1.0f), 0.0f), 513.0f);

    int ii0 = (int)gi;            // truncation == astype(int32) for gi >= 0
    int jj0 = (int)gj;
    float fi = gi - (float)ii0;   // weight for di=1 row
    float fj = gj - (float)jj0;
    float wi0 = 1.0f - fi, wi1 = fi;
    float wj0 = 1.0f - fj, wj1 = fj;

    // Output coords: (ii-1, jj-1); valid iff inside [0,512)
    int oi0 = ii0 - 1, oi1 = ii0;
    int oj0 = jj0 - 1, oj1 = jj0;
    bool vi0 = (unsigned)oi0 < (unsigned)Hn;
    bool vi1 = (unsigned)oi1 < (unsigned)Hn;
    bool vj0 = (unsigned)oj0 < (unsigned)Wn;
    bool vj1 = (unsigned)oj1 < (unsigned)Wn;

    bool  v00 = vi0 && vj0,          v01 = vi0 && vj1;
    bool  v10 = vi1 && vj0,          v11 = vi1 && vj1;
    int   o00 = oi0 * Wn + oj0,      o01 = oi0 * Wn + oj1;
    int   o10 = oi1 * Wn + oj0,      o11 = oi1 * Wn + oj1;
    float w00 = wi0 * wj0,           w01 = wi0 * wj1;
    float w10 = wi1 * wj0,           w11 = wi1 * wj1;

    int b   = p >> 18;          // p / HWn
    int pix = p & (HWn - 1);

    // D accumulation (4 atomics per pixel)
    float* Db = g_D + b * HWn;
    if (v00) atomicAdd(Db + o00, w00);
    if (v01) atomicAdd(Db + o01, w01);
    if (v10) atomicAdd(Db + o10, w10);
    if (v11) atomicAdd(Db + o11, w11);

    // Channel loop: 16 coalesced loads of x, up to 64 RED.ADDs into out.
    const float* xp = x + (size_t)b * Cn * HWn + pix;
    float*       op = out + (size_t)b * Cn * HWn;
#pragma unroll
    for (int c = 0; c < Cn; c++) {
        float xv = __ldg(xp + c * HWn);
        float* o = op + c * HWn;
        if (v00) atomicAdd(o + o00, xv * w00);
        if (v01) atomicAdd(o + o01, xv * w01);
        if (v10) atomicAdd(o + o10, xv * w10);
        if (v11) atomicAdd(o + o11, xv * w11);
    }
}

// ---------------------------------------------------------------------------
// Kernel 3: normalize. One thread per 4 pixels; reads D once (float4),
// applies out = valid ? A/(D+EPS) : 1.0 to all 16 channels with float4 RW.
// ---------------------------------------------------------------------------
__global__ void normalize_kernel(float4* __restrict__ out) {
    int q = blockIdx.x * blockDim.x + threadIdx.x;
    const int nq = NPIX / 4;      // 262144
    if (q >= nq) return;

    int b  = q >> 16;             // HWn/4 = 65536 quads per batch
    int pq = q & 65535;

    float4 d = reinterpret_cast<const float4*>(g_D)[q];
    float4 r, hf;
    bool bx = d.x > EPSF, by = d.y > EPSF, bz = d.z > EPSF, bw = d.w > EPSF;
    r.x  = bx ? 1.0f / (d.x + EPSF) : 0.0f;  hf.x = bx ? 0.0f : 1.0f;
    r.y  = by ? 1.0f / (d.y + EPSF) : 0.0f;  hf.y = by ? 0.0f : 1.0f;
    r.z  = bz ? 1.0f / (d.z + EPSF) : 0.0f;  hf.z = bz ? 0.0f : 1.0f;
    r.w  = bw ? 1.0f / (d.w + EPSF) : 0.0f;  hf.w = bw ? 0.0f : 1.0f;

    float4* ob = out + (size_t)(b * Cn) * 65536 + pq;
#pragma unroll
    for (int c = 0; c < Cn; c++) {
        float4 v = ob[(size_t)c * 65536];
        v.x = fmaf(v.x, r.x, hf.x);
        v.y = fmaf(v.y, r.y, hf.y);
        v.z = fmaf(v.z, r.z, hf.z);
        v.w = fmaf(v.w, r.w, hf.w);
        ob[(size_t)c * 65536] = v;
    }
}

// ---------------------------------------------------------------------------
extern "C" void kernel_launch(void* const* d_in, const int* in_sizes, int n_in,
                              void* d_out, int out_size) {
    const float* x    = (const float*)d_in[0];
    const float* grid = (const float*)d_in[1];
    float*       out  = (float*)d_out;

    {
        int total = NOUT / 4 + NPIX / 4;
        zero_kernel<<<(total + 255) / 256, 256>>>((float4*)out);
    }
    scatter_kernel<<<NPIX / 256, 256>>>(x, grid, out);
    normalize_kernel<<<(NPIX / 4 + 255) / 256, 256>>>((float4*)out);
}

// round 2
// speedup vs baseline: 2.2769x; 2.2769x over previous
#include <cuda_runtime.h>
#include <cstdint>

#define Bn 4
#define Cn 16
#define Hn 512
#define Wn 512
#define HWn (Hn*Wn)        // 262144
#define NPIX (Bn*HWn)      // 1048576
#define NOUT (Bn*Cn*HWn)   // 16777216
#define EPSF 1e-10f

// Channel-contiguous accumulator A': layout [pixel][channel], pixel = b*HWn + (i*W+j).
// 64 MB static scratch. Per-corner contributions are 64B contiguous -> vec4 atomics.
__device__ float g_A[NOUT];
// Weight-sum accumulator D (B,H,W). 4 MB.
__device__ float g_D[NPIX];

// ---------------------------------------------------------------------------
// Kernel 1: zero scratch A' and D (output is fully overwritten by normalize).
// ---------------------------------------------------------------------------
__global__ void zero_kernel() {
    const int n_a4 = NOUT / 4;   // 4194304
    const int n_d4 = NPIX / 4;   // 262144
    int idx = blockIdx.x * blockDim.x + threadIdx.x;
    float4 z = make_float4(0.f, 0.f, 0.f, 0.f);
    if (idx < n_a4) {
        reinterpret_cast<float4*>(g_A)[idx] = z;
    } else if (idx < n_a4 + n_d4) {
        reinterpret_cast<float4*>(g_D)[idx - n_a4] = z;
    }
}

// vec4 global reduction (sm_90+): one RED message for 4 contiguous floats.
__device__ __forceinline__ void red4(float* addr, float a, float b, float c, float d) {
    asm volatile("red.global.add.v4.f32 [%0], {%1,%2,%3,%4};"
                 :: "l"(addr), "f"(a), "f"(b), "f"(c), "f"(d) : "memory");
}

__device__ __forceinline__ void emit_corner(bool v, float* base, float w,
                                            const float* xv) {
    if (!v) return;
#pragma unroll
    for (int g = 0; g < 4; g++) {
        red4(base + g * 4, xv[4*g+0] * w, xv[4*g+1] * w,
                           xv[4*g+2] * w, xv[4*g+3] * w);
    }
}

// ---------------------------------------------------------------------------
// Kernel 2: scatter. One thread per source pixel. 16 vec4 REDs + 4 scalar.
// ---------------------------------------------------------------------------
__global__ void scatter_kernel(const float* __restrict__ x,
                               const float* __restrict__ grid) {
    int p = blockIdx.x * blockDim.x + threadIdx.x;
    if (p >= NPIX) return;

    float2 gv = reinterpret_cast<const float2*>(grid)[p];

    float g0 = (gv.x + 1.0f) * 0.5f;
    float g1 = (gv.y + 1.0f) * 0.5f;
    float gi = fminf(fmaxf(fmaf(g0, 512.0f, 1.0f), 0.0f), 513.0f);
    float gj = fminf(fmaxf(fmaf(g1, 512.0f, 1.0f), 0.0f), 513.0f);

    int ii0 = (int)gi;
    int jj0 = (int)gj;
    float fi = gi - (float)ii0;
    float fj = gj - (float)jj0;
    float wi0 = 1.0f - fi, wi1 = fi;
    float wj0 = 1.0f - fj, wj1 = fj;

    int oi0 = ii0 - 1, oi1 = ii0;
    int oj0 = jj0 - 1, oj1 = jj0;
    bool vi0 = (unsigned)oi0 < (unsigned)Hn;
    bool vi1 = (unsigned)oi1 < (unsigned)Hn;
    bool vj0 = (unsigned)oj0 < (unsigned)Wn;
    bool vj1 = (unsigned)oj1 < (unsigned)Wn;

    bool  v00 = vi0 && vj0,       v01 = vi0 && vj1;
    bool  v10 = vi1 && vj0,       v11 = vi1 && vj1;
    int   o00 = oi0 * Wn + oj0,   o01 = oi0 * Wn + oj1;
    int   o10 = oi1 * Wn + oj0,   o11 = oi1 * Wn + oj1;
    float w00 = wi0 * wj0,        w01 = wi0 * wj1;
    float w10 = wi1 * wj0,        w11 = wi1 * wj1;

    int b   = p >> 18;
    int pix = p & (HWn - 1);

    // D accumulation (4 scalar atomics)
    float* Db = g_D + b * HWn;
    if (v00) atomicAdd(Db + o00, w00);
    if (v01) atomicAdd(Db + o01, w01);
    if (v10) atomicAdd(Db + o10, w10);
    if (v11) atomicAdd(Db + o11, w11);

    // Load the 16 channel values (coalesced per plane)
    const float* xp = x + (size_t)b * Cn * HWn + pix;
    float xv[16];
#pragma unroll
    for (int c = 0; c < Cn; c++) xv[c] = __ldg(xp + c * HWn);

    // Scatter into channel-contiguous scratch: 4 x vec4 RED per corner
    float* Ab = g_A + (size_t)b * HWn * Cn;
    emit_corner(v00, Ab + (size_t)o00 * Cn, w00, xv);
    emit_corner(v01, Ab + (size_t)o01 * Cn, w01, xv);
    emit_corner(v10, Ab + (size_t)o10 * Cn, w10, xv);
    emit_corner(v11, Ab + (size_t)o11 * Cn, w11, xv);
}

// ---------------------------------------------------------------------------
// Kernel 3: normalize + transpose [pix][c] -> [c][pix]. One thread per 4 pixels.
// ---------------------------------------------------------------------------
__global__ void normalize_kernel(float4* __restrict__ out4) {
    int q = blockIdx.x * blockDim.x + threadIdx.x;
    if (q >= NPIX / 4) return;

    float4 d = reinterpret_cast<const float4*>(g_D)[q];
    float4 r, hf;
    bool bx = d.x > EPSF, by = d.y > EPSF, bz = d.z > EPSF, bw = d.w > EPSF;
    r.x = bx ? 1.0f / (d.x + EPSF) : 0.0f;  hf.x = bx ? 0.0f : 1.0f;
    r.y = by ? 1.0f / (d.y + EPSF) : 0.0f;  hf.y = by ? 0.0f : 1.0f;
    r.z = bz ? 1.0f / (d.z + EPSF) : 0.0f;  hf.z = bz ? 0.0f : 1.0f;
    r.w = bw ? 1.0f / (d.w + EPSF) : 0.0f;  hf.w = bw ? 0.0f : 1.0f;

    int p0  = q * 4;                 // first of 4 consecutive pixels (same batch/row)
    int b   = p0 >> 18;
    int pix = p0 & (HWn - 1);

    const float4* A0 = reinterpret_cast<const float4*>(g_A + (size_t)p0 * Cn);
    float4* ob = out4 + ((size_t)b * Cn * HWn + pix) / 4;

#pragma unroll
    for (int g = 0; g < 4; g++) {
        float4 a0 = A0[0 * 4 + g];   // pixel p0, channels 4g..4g+3
        float4 a1 = A0[1 * 4 + g];
        float4 a2 = A0[2 * 4 + g];
        float4 a3 = A0[3 * 4 + g];

        float4 v0 = make_float4(fmaf(a0.x, r.x, hf.x), fmaf(a1.x, r.y, hf.y),
                                fmaf(a2.x, r.z, hf.z), fmaf(a3.x, r.w, hf.w));
        float4 v1 = make_float4(fmaf(a0.y, r.x, hf.x), fmaf(a1.y, r.y, hf.y),
                                fmaf(a2.y, r.z, hf.z), fmaf(a3.y, r.w, hf.w));
        float4 v2 = make_float4(fmaf(a0.z, r.x, hf.x), fmaf(a1.z, r.y, hf.y),
                                fmaf(a2.z, r.z, hf.z), fmaf(a3.z, r.w, hf.w));
        float4 v3 = make_float4(fmaf(a0.w, r.x, hf.x), fmaf(a1.w, r.y, hf.y),
                                fmaf(a2.w, r.z, hf.z), fmaf(a3.w, r.w, hf.w));

        ob[(size_t)(4 * g + 0) * (HWn / 4)] = v0;
        ob[(size_t)(4 * g + 1) * (HWn / 4)] = v1;
        ob[(size_t)(4 * g + 2) * (HWn / 4)] = v2;
        ob[(size_t)(4 * g + 3) * (HWn / 4)] = v3;
    }
}

// ---------------------------------------------------------------------------
extern "C" void kernel_launch(void* const* d_in, const int* in_sizes, int n_in,
                              void* d_out, int out_size) {
    const float* x    = (const float*)d_in[0];
    const float* grid = (const float*)d_in[1];
    float*       out  = (float*)d_out;

    {
        int total = NOUT / 4 + NPIX / 4;
        zero_kernel<<<(total + 255) / 256, 256>>>();
    }
    scatter_kernel<<<NPIX / 256, 256>>>(x, grid);
    normalize_kernel<<<(NPIX / 4 + 255) / 256, 256>>>((float4*)out);
}